// round 2
// baseline (speedup 1.0000x reference)
#include <cuda_runtime.h>
#include <math.h>

#define BC    1024      // 8 * 128 merged batch*channel
#define LIN   65536
#define LOUT  16384
#define KNB   9

// 256 MB transpose scratch: xt[bc>>5][i][bc&31]
__device__ float g_xt[(size_t)LIN * BC];

// ---------------------------------------------------------------------------
// Kernel 1: transpose x[bc][i]  ->  g_xt[chunk][i][lane],  chunk = bc>>5
// Tile: 32 bc x 256 i per CTA. Coalesced float4 reads, coalesced 128B writes.
// ---------------------------------------------------------------------------
__global__ __launch_bounds__(256) void transpose_kernel(const float* __restrict__ x) {
    __shared__ float tile[32][257];   // +1 pad: conflict-free column reads

    const int iBase  = blockIdx.x * 256;
    const int bcBase = blockIdx.y * 32;
    const int t = threadIdx.x;

    // ---- load: 8 threads per bc-row, each loads 8 float4 (coalesced 128B groups)
    const int r  = t >> 3;   // bc row within tile, 0..31
    const int l8 = t & 7;    // 0..7
    const float4* x4 = (const float4*)(x + (size_t)(bcBase + r) * LIN + iBase);
    #pragma unroll
    for (int m = 0; m < 8; m++) {
        float4 v = x4[l8 + 8 * m];
        int c = (l8 + 8 * m) * 4;
        tile[r][c + 0] = v.x;
        tile[r][c + 1] = v.y;
        tile[r][c + 2] = v.z;
        tile[r][c + 3] = v.w;
    }
    __syncthreads();

    // ---- store: warp writes one i-row (32 bc values = 128B contiguous) at a time
    const int w    = t >> 5;
    const int lane = t & 31;
    float* dst = g_xt + (size_t)blockIdx.y * LIN * 32;   // chunk base
    #pragma unroll
    for (int m = 0; m < 32; m++) {
        int i = w * 32 + m;
        // tile[lane][i]: addr = lane*257 + i, stride 257 across lanes -> conflict-free
        dst[(size_t)(iBase + i) * 32 + lane] = tile[lane][i];
    }
}

// ---------------------------------------------------------------------------
// Kernel 2: gather-max.
// CTA = (l tile of 256) x (bc chunk of 32). lane = bc -> every gather is a
// fully-coalesced 128B line from g_xt. Output staged in padded smem so the
// final global writes are coalesced along l.
// ---------------------------------------------------------------------------
__global__ __launch_bounds__(256) void gather_kernel(const int* __restrict__ nb,
                                                     float* __restrict__ out) {
    __shared__ int   s_idx[KNB * 256];     // 9 KB
    __shared__ float s_out[256 * 33];      // 33 KB, pad 33 for conflict-free

    const int lBase = blockIdx.x * 256;
    const int chunk = blockIdx.y;
    const int t = threadIdx.x;

    // load index tile (int32; values < 65536)
    for (int j = t; j < KNB * 256; j += 256) {
        int k  = j >> 8;
        int ll = j & 255;
        s_idx[j] = nb[(size_t)k * LOUT + lBase + ll];
    }
    __syncthreads();

    const int w    = t >> 5;
    const int lane = t & 31;
    const float* xb = g_xt + (size_t)chunk * LIN * 32 + lane;

    // each warp handles 32 l's; 2 at a time for MLP (18 loads in flight)
    for (int m = 0; m < 32; m += 2) {
        const int ll0 = w * 32 + m;
        const int ll1 = ll0 + 1;
        float a0 = -INFINITY, a1 = -INFINITY;
        #pragma unroll
        for (int k = 0; k < KNB; k++) {
            int i0 = s_idx[k * 256 + ll0];     // broadcast LDS (same addr all lanes)
            int i1 = s_idx[k * 256 + ll1];
            float v0 = __ldg(xb + (size_t)i0 * 32);   // 128B coalesced gather
            float v1 = __ldg(xb + (size_t)i1 * 32);
            a0 = fmaxf(a0, v0);
            a1 = fmaxf(a1, v1);
        }
        s_out[ll0 * 33 + lane] = a0;
        s_out[ll1 * 33 + lane] = a1;
    }
    __syncthreads();

    // writeback: thread t owns l = lBase + t; loop bc rows -> 1KB coalesced per row
    float* ob = out + (size_t)(chunk * 32) * LOUT + lBase + t;
    #pragma unroll
    for (int bc = 0; bc < 32; bc++) {
        // s_out[t][bc]: addr = t*33 + bc, stride 33 across threads -> conflict-free
        ob[(size_t)bc * LOUT] = s_out[t * 33 + bc];
    }
}

// ---------------------------------------------------------------------------
extern "C" void kernel_launch(void* const* d_in, const int* in_sizes, int n_in,
                              void* d_out, int out_size) {
    const float* x   = (const float*)d_in[0];
    const int*   nb  = (const int*)d_in[1];
    float*       out = (float*)d_out;

    (void)in_sizes; (void)n_in; (void)out_size;

    transpose_kernel<<<dim3(LIN / 256, BC / 32), 256>>>(x);
    gather_kernel<<<dim3(LOUT / 256, BC / 32), 256>>>(nb, out);
}

// round 3
// speedup vs baseline: 1.0327x; 1.0327x over previous
#include <cuda_runtime.h>
#include <math.h>

#define BC    1024      // 8 * 128 merged batch*channel
#define LIN   65536
#define LOUT  16384
#define KNB   9
#define NCHUNK (BC / 32)   // 32

// 256 MB transpose scratch: xt[bc>>5][i][bc&31]
__device__ float g_xt[(size_t)LIN * BC];

// ---------------------------------------------------------------------------
// Kernel 1: transpose x[bc][i]  ->  g_xt[chunk][i][lane],  chunk = bc>>5
// Tile: 32 bc x 256 i per CTA. float4 reads, float4 (STG.128) writes.
// ---------------------------------------------------------------------------
__global__ __launch_bounds__(256) void transpose_kernel(const float* __restrict__ x) {
    __shared__ float tile[32][257];   // +1 pad: conflict-free column reads

    const int iBase  = blockIdx.x * 256;
    const int bcBase = blockIdx.y * 32;
    const int t = threadIdx.x;

    // ---- load: 8 threads per bc-row, each loads 8 float4 (coalesced 128B groups)
    const int r  = t >> 3;   // bc row within tile, 0..31
    const int l8 = t & 7;    // 0..7
    const float4* x4 = (const float4*)(x + (size_t)(bcBase + r) * LIN + iBase);
    #pragma unroll
    for (int m = 0; m < 8; m++) {
        float4 v = x4[l8 + 8 * m];
        int c = (l8 + 8 * m) * 4;
        tile[r][c + 0] = v.x;
        tile[r][c + 1] = v.y;
        tile[r][c + 2] = v.z;
        tile[r][c + 3] = v.w;
    }
    __syncthreads();

    // ---- store: warp w covers i-rows w*32..w*32+31, 4 rows per step.
    // Each thread: 4 column LDS (banks (4c+iq)%32 cover 0..31 once -> conflict-free)
    // + 1 STG.128. Warp store = 4 x 128B contiguous rows.
    const int w    = t >> 5;
    const int lane = t & 31;
    const int c4 = (lane & 7) * 4;   // bc group base 0,4,..,28
    const int iq = lane >> 3;        // 0..3 (i-row within step)
    float* dst = g_xt + (size_t)blockIdx.y * LIN * 32;   // chunk base
    #pragma unroll
    for (int s = 0; s < 8; s++) {
        int i = w * 32 + s * 4 + iq;
        float4 v;
        v.x = tile[c4 + 0][i];
        v.y = tile[c4 + 1][i];
        v.z = tile[c4 + 2][i];
        v.w = tile[c4 + 3][i];
        *(float4*)(dst + (size_t)(iBase + i) * 32 + c4) = v;
    }
}

// ---------------------------------------------------------------------------
// Kernel 2: gather-max.
// CTA = (l tile of 256) x (bc chunk of 32). lane = bc -> every gather is a
// fully-coalesced 128B line from g_xt. Index tile lives in registers
// (9/lane) and is broadcast with shfl -> no s_idx smem, 6 CTAs/SM.
// 4 l's in flight -> 36 outstanding LDGs per warp.
// ---------------------------------------------------------------------------
__global__ __launch_bounds__(256) void gather_kernel(const int* __restrict__ nb,
                                                     float* __restrict__ out) {
    __shared__ float s_out[256 * 33];      // ~33.8 KB, pad 33: conflict-free

    const int lBase = blockIdx.x * 256;
    const int chunk = (NCHUNK - 1) - blockIdx.y;   // reverse: hit transpose-warm L2
    const int t    = threadIdx.x;
    const int w    = t >> 5;
    const int lane = t & 31;

    // each lane owns index column l = w*32 + lane (9 regs)
    int myIdx[KNB];
    #pragma unroll
    for (int k = 0; k < KNB; k++)
        myIdx[k] = nb[(size_t)k * LOUT + lBase + w * 32 + lane];

    const float* xb = g_xt + (size_t)chunk * LIN * 32 + lane;

    // warp handles 32 l's; 4 at a time -> 36 loads in flight
    #pragma unroll 1
    for (int m = 0; m < 32; m += 4) {
        float a0, a1, a2, a3;
        {   // k = 0 initializes (no -inf dependency)
            int i0 = __shfl_sync(0xffffffffu, myIdx[0], m + 0);
            int i1 = __shfl_sync(0xffffffffu, myIdx[0], m + 1);
            int i2 = __shfl_sync(0xffffffffu, myIdx[0], m + 2);
            int i3 = __shfl_sync(0xffffffffu, myIdx[0], m + 3);
            a0 = __ldg(xb + (size_t)i0 * 32);
            a1 = __ldg(xb + (size_t)i1 * 32);
            a2 = __ldg(xb + (size_t)i2 * 32);
            a3 = __ldg(xb + (size_t)i3 * 32);
        }
        #pragma unroll
        for (int k = 1; k < KNB; k++) {
            int i0 = __shfl_sync(0xffffffffu, myIdx[k], m + 0);
            int i1 = __shfl_sync(0xffffffffu, myIdx[k], m + 1);
            int i2 = __shfl_sync(0xffffffffu, myIdx[k], m + 2);
            int i3 = __shfl_sync(0xffffffffu, myIdx[k], m + 3);
            float v0 = __ldg(xb + (size_t)i0 * 32);
            float v1 = __ldg(xb + (size_t)i1 * 32);
            float v2 = __ldg(xb + (size_t)i2 * 32);
            float v3 = __ldg(xb + (size_t)i3 * 32);
            a0 = fmaxf(a0, v0);
            a1 = fmaxf(a1, v1);
            a2 = fmaxf(a2, v2);
            a3 = fmaxf(a3, v3);
        }
        int ll = w * 32 + m;
        s_out[(ll + 0) * 33 + lane] = a0;
        s_out[(ll + 1) * 33 + lane] = a1;
        s_out[(ll + 2) * 33 + lane] = a2;
        s_out[(ll + 3) * 33 + lane] = a3;
    }
    __syncthreads();

    // writeback: warp w owns bc rows w*4 .. w*4+3; each row = 256 l's,
    // written as 8 x 128B coalesced stores. smem reads stride 33 -> conflict-free.
    #pragma unroll
    for (int r = 0; r < 4; r++) {
        int bc = w * 4 + r;
        float* ob = out + (size_t)(chunk * 32 + bc) * LOUT + lBase;
        #pragma unroll
        for (int j = 0; j < 8; j++) {
            int l = lane + 32 * j;
            ob[l] = s_out[l * 33 + bc];
        }
    }
}

// ---------------------------------------------------------------------------
extern "C" void kernel_launch(void* const* d_in, const int* in_sizes, int n_in,
                              void* d_out, int out_size) {
    const float* x   = (const float*)d_in[0];
    const int*   nb  = (const int*)d_in[1];
    float*       out = (float*)d_out;

    (void)in_sizes; (void)n_in; (void)out_size;

    transpose_kernel<<<dim3(LIN / 256, BC / 32), 256>>>(x);
    gather_kernel<<<dim3(LOUT / 256, NCHUNK), 256>>>(nb, out);
}

// round 4
// speedup vs baseline: 1.4702x; 1.4237x over previous
#include <cuda_runtime.h>
#include <cuda_fp16.h>
#include <math.h>

#define BC     1024     // 8 * 128 merged batch*channel
#define LIN    65536
#define LOUT   16384
#define KNB    9
#define CW     64       // bc per chunk (fp16 -> 128B line)
#define NCHUNK (BC / CW)   // 16

// 128 MB fp16 transpose scratch: xt[bc/64][i][bc%64]
__device__ __half g_xt[(size_t)LIN * BC];

// ---------------------------------------------------------------------------
// Kernel 1: transpose+convert x[bc][i] (fp32) -> g_xt[chunk][i][bc2] (fp16)
// Tile: 64 bc x 128 i per CTA, 256 threads.
// ---------------------------------------------------------------------------
__global__ __launch_bounds__(256) void transpose_kernel(const float* __restrict__ x) {
    __shared__ float tile[64][129];   // pad: column reads 2-way max

    const int iBase  = blockIdx.x * 128;
    const int bcBase = blockIdx.y * CW;
    const int t = threadIdx.x;

    // ---- load: 4 threads per bc-row, each loads 8 float4 (64B groups per row)
    const int r = t >> 2;    // bc row in tile, 0..63
    const int q = t & 3;     // 0..3
    const float4* x4 = (const float4*)(x + (size_t)(bcBase + r) * LIN + iBase);
    #pragma unroll
    for (int m = 0; m < 8; m++) {
        float4 v = x4[q + 4 * m];
        int c = (q + 4 * m) * 4;
        tile[r][c + 0] = v.x;
        tile[r][c + 1] = v.y;
        tile[r][c + 2] = v.z;
        tile[r][c + 3] = v.w;
    }
    __syncthreads();

    // ---- store: warp w owns i-rows w*16..w*16+15. Per row the warp writes
    // 64 halves = 128B contiguous (lane -> half2 of bc pair 2*lane).
    const int w    = t >> 5;
    const int lane = t & 31;
    __half2* dst = (__half2*)(g_xt + (size_t)blockIdx.y * LIN * CW) + lane;
    #pragma unroll
    for (int s = 0; s < 16; s++) {
        int i = w * 16 + s;
        __half2 v = __floats2half2_rn(tile[2 * lane][i], tile[2 * lane + 1][i]);
        dst[(size_t)(iBase + i) * 32] = v;
    }
}

// ---------------------------------------------------------------------------
// Kernel 2: gather-max over fp16 chunks.
// CTA = (l tile of 256) x (chunk of 64 bc). lane gathers half2 -> warp load =
// 256B fully-used contiguous. Index broadcast via shfl. 4 l's in flight.
// ---------------------------------------------------------------------------
__global__ __launch_bounds__(256) void gather_kernel(const int* __restrict__ nb,
                                                     float* __restrict__ out) {
    __shared__ __half s_out[256 * 66];     // 33.8 KB, pad 66: conflict-free

    const int lBase = blockIdx.x * 256;
    const int chunk = (NCHUNK - 1) - blockIdx.y;   // reverse: transpose-warm L2
    const int t    = threadIdx.x;
    const int w    = t >> 5;
    const int lane = t & 31;

    // lane owns index column l = w*32 + lane (9 regs)
    int myIdx[KNB];
    #pragma unroll
    for (int k = 0; k < KNB; k++)
        myIdx[k] = nb[(size_t)k * LOUT + lBase + w * 32 + lane];

    const __half2* xb = (const __half2*)(g_xt + (size_t)chunk * LIN * CW) + lane;

    #pragma unroll 1
    for (int m = 0; m < 32; m += 4) {
        __half2 a0, a1, a2, a3;
        {   // k = 0 initializes
            int i0 = __shfl_sync(0xffffffffu, myIdx[0], m + 0);
            int i1 = __shfl_sync(0xffffffffu, myIdx[0], m + 1);
            int i2 = __shfl_sync(0xffffffffu, myIdx[0], m + 2);
            int i3 = __shfl_sync(0xffffffffu, myIdx[0], m + 3);
            a0 = __ldg(xb + (size_t)i0 * 32);
            a1 = __ldg(xb + (size_t)i1 * 32);
            a2 = __ldg(xb + (size_t)i2 * 32);
            a3 = __ldg(xb + (size_t)i3 * 32);
        }
        #pragma unroll
        for (int k = 1; k < KNB; k++) {
            int i0 = __shfl_sync(0xffffffffu, myIdx[k], m + 0);
            int i1 = __shfl_sync(0xffffffffu, myIdx[k], m + 1);
            int i2 = __shfl_sync(0xffffffffu, myIdx[k], m + 2);
            int i3 = __shfl_sync(0xffffffffu, myIdx[k], m + 3);
            __half2 v0 = __ldg(xb + (size_t)i0 * 32);
            __half2 v1 = __ldg(xb + (size_t)i1 * 32);
            __half2 v2 = __ldg(xb + (size_t)i2 * 32);
            __half2 v3 = __ldg(xb + (size_t)i3 * 32);
            a0 = __hmax2(a0, v0);
            a1 = __hmax2(a1, v1);
            a2 = __hmax2(a2, v2);
            a3 = __hmax2(a3, v3);
        }
        int ll = w * 32 + m;
        __half2* so = (__half2*)s_out;
        so[(ll + 0) * 33 + lane] = a0;
        so[(ll + 1) * 33 + lane] = a1;
        so[(ll + 2) * 33 + lane] = a2;
        so[(ll + 3) * 33 + lane] = a3;
    }
    __syncthreads();

    // writeback: thread t owns l = lBase + t; loop 64 bc rows.
    // smem read word = (66t + bc)>>1 = 33t + bc/2 -> bank (t + bc/2)%32: conflict-free.
    float* ob = out + (size_t)(chunk * CW) * LOUT + lBase + t;
    #pragma unroll
    for (int bc = 0; bc < CW; bc++) {
        ob[(size_t)bc * LOUT] = __half2float(s_out[t * 66 + bc]);
    }
}

// ---------------------------------------------------------------------------
extern "C" void kernel_launch(void* const* d_in, const int* in_sizes, int n_in,
                              void* d_out, int out_size) {
    const float* x   = (const float*)d_in[0];
    const int*   nb  = (const int*)d_in[1];
    float*       out = (float*)d_out;

    (void)in_sizes; (void)n_in; (void)out_size;

    transpose_kernel<<<dim3(LIN / 128, BC / CW), 256>>>(x);
    gather_kernel<<<dim3(LOUT / 256, NCHUNK), 256>>>(nb, out);
}

// round 6
// speedup vs baseline: 1.8435x; 1.2539x over previous
#include <cuda_runtime.h>
#include <cuda_fp16.h>
#include <math.h>

#define BC     1024     // 8 * 128 merged batch*channel
#define LIN    65536
#define LOUT   16384
#define KNB    9
#define CW     64       // bc per chunk (fp16 -> 128B gather line)
#define NCHUNK (BC / CW)   // 16

// 128 MB fp16 transpose scratch: xt[bc/64][i][bc%64]
__device__ __half g_xt[(size_t)LIN * BC];

// ---------------------------------------------------------------------------
// Kernel 1: transpose+convert x[bc][i] (fp32) -> g_xt[chunk][i][bc2] (fp16)
// Tile: 64 bc x 64 i, 256 threads, smem 16.6 KB -> 8 CTAs/SM.
// Load phase uses scalar STS (row stride 65 floats is NOT 16B aligned; the
// float4 STS variant traps with misaligned address).
// ---------------------------------------------------------------------------
__global__ __launch_bounds__(256) void transpose_kernel(const float* __restrict__ x) {
    __shared__ float tile[64][65];   // pad 65: store-phase column reads 2-way max

    const int iBase  = blockIdx.x * 64;
    const int bcBase = blockIdx.y * CW;
    const int t = threadIdx.x;

    // ---- load: 4 threads per bc-row, each 4 x LDG.128 + scalar STS
    const int r = t >> 2;    // bc row 0..63
    const int q = t & 3;     // 0..3
    const float4* x4 = (const float4*)(x + (size_t)(bcBase + r) * LIN + iBase);
    #pragma unroll
    for (int m = 0; m < 4; m++) {
        float4 v = x4[q + 4 * m];
        int c = (q + 4 * m) * 4;
        tile[r][c + 0] = v.x;
        tile[r][c + 1] = v.y;
        tile[r][c + 2] = v.z;
        tile[r][c + 3] = v.w;
    }
    __syncthreads();

    // ---- store: warp w owns i = w*8 .. w*8+7. Per i the warp writes
    // 64 halves = 128B contiguous (lane -> half2 of bc pair 2*lane).
    const int w    = t >> 5;
    const int lane = t & 31;
    __half2* dst = (__half2*)(g_xt + (size_t)blockIdx.y * LIN * CW) + lane;
    #pragma unroll
    for (int s = 0; s < 8; s++) {
        int i = w * 8 + s;
        // tile[2lane][i]: bank = (2lane*65 + i)%32 = (2lane + i)%32 -> 2-way max
        __half2 v = __floats2half2_rn(tile[2 * lane][i], tile[2 * lane + 1][i]);
        dst[(size_t)(iBase + i) * 32] = v;
    }
}

// ---------------------------------------------------------------------------
// Kernel 2: gather-max over fp16 chunks.
// CTA = (l tile of 128) x (chunk of 64 bc). lane gathers half2 -> warp load =
// 128B fully-used. Per l: 9 loads batched into regs, tree-reduce -> high MLP.
// smem 16.9 KB -> 6 CTAs/SM.
// ---------------------------------------------------------------------------
__global__ __launch_bounds__(256) void gather_kernel(const int* __restrict__ nb,
                                                     float* __restrict__ out) {
    __shared__ __half s_out[128 * 66];     // 128 l x 64 bc, pad 66 -> 16.9 KB

    const int lBase = blockIdx.x * 128;
    const int chunk = (NCHUNK - 1) - blockIdx.y;   // reverse: transpose-warm L2
    const int t    = threadIdx.x;
    const int w    = t >> 5;       // warp owns 16 l's
    const int lane = t & 31;

    // lanes 0-15 own index column l = w*16 + lane (lanes 16-31 mirror)
    int myIdx[KNB];
    const int myL = lBase + w * 16 + (lane & 15);
    #pragma unroll
    for (int k = 0; k < KNB; k++)
        myIdx[k] = __ldg(nb + (size_t)k * LOUT + myL);

    const __half2* xb = (const __half2*)(g_xt + (size_t)chunk * LIN * CW) + lane;

    #pragma unroll 1
    for (int m = 0; m < 16; m += 4) {
        __half2 acc[4];
        #pragma unroll
        for (int j = 0; j < 4; j++) {
            // 9 independent gathers for this l, issued back-to-back
            __half2 v[KNB];
            #pragma unroll
            for (int k = 0; k < KNB; k++) {
                int i = __shfl_sync(0xffffffffu, myIdx[k], m + j);
                v[k] = __ldg(xb + (size_t)i * 32);
            }
            // tree reduce (depth 4)
            __half2 m01 = __hmax2(v[0], v[1]);
            __half2 m23 = __hmax2(v[2], v[3]);
            __half2 m45 = __hmax2(v[4], v[5]);
            __half2 m67 = __hmax2(v[6], v[7]);
            m01 = __hmax2(m01, m23);
            m45 = __hmax2(m45, m67);
            acc[j] = __hmax2(__hmax2(m01, m45), v[8]);
        }
        const int ll = w * 16 + m;
        __half2* so = (__half2*)s_out;
        #pragma unroll
        for (int j = 0; j < 4; j++) {
            // word = 33*(ll+j) + lane -> bank (ll+j+lane)%32: conflict-free
            so[(ll + j) * 33 + lane] = acc[j];
        }
    }
    __syncthreads();

    // writeback: t -> l = t&127, bc group (t>>7)*32; 128B coalesced stores.
    const int l = t & 127;
    const int g = (t >> 7) * 32;
    float* ob = out + (size_t)(chunk * CW + g) * LOUT + lBase + l;
    #pragma unroll
    for (int b = 0; b < 32; b++)
        ob[(size_t)b * LOUT] = __half2float(s_out[l * 66 + g + b]);
}

// ---------------------------------------------------------------------------
extern "C" void kernel_launch(void* const* d_in, const int* in_sizes, int n_in,
                              void* d_out, int out_size) {
    const float* x   = (const float*)d_in[0];
    const int*   nb  = (const int*)d_in[1];
    float*       out = (float*)d_out;

    (void)in_sizes; (void)n_in; (void)out_size;

    transpose_kernel<<<dim3(LIN / 64, BC / CW), 256>>>(x);
    gather_kernel<<<dim3(LOUT / 128, NCHUNK), 256>>>(nb, out);
}

// round 7
// speedup vs baseline: 1.9064x; 1.0342x over previous
#include <cuda_runtime.h>
#include <cuda_fp16.h>
#include <math.h>

#define BC        1024       // 8 * 128 merged batch*channel
#define LIN       65536
#define LOUT      16384
#define KNB       9
#define CHUNK_BC  256        // bc per pipeline chunk
#define NCHUNK    (BC / CHUNK_BC)          // 4
#define CHUNK_EL  ((size_t)LIN * CHUNK_BC) // halves per chunk buffer (32 MB)

// 64 MB ping-pong scratch, L2-resident: buf[p][i][bcp], bcp < 256
__device__ __half g_buf[2 * CHUNK_EL];

// ---------------------------------------------------------------------------
// Combined kernel: gather of chunk gc (reads buf[gc&1]) runs concurrently
// with transpose of chunk tc (writes buf[tc&1]). Either may be -1 (skipped).
// Gather CTAs get the low blockIdx range (scheduled first -> hit warm L2).
// ---------------------------------------------------------------------------
__global__ __launch_bounds__(256) void pool_kernel(const float* __restrict__ x,
                                                   const int*   __restrict__ nb,
                                                   float*       __restrict__ out,
                                                   int gc, int tc) {
    __shared__ __align__(16) char sm_raw[16896];   // union: gather 16.9KB / transpose 16.6KB

    const int t    = threadIdx.x;
    const int w    = t >> 5;
    const int lane = t & 31;
    const int gGrid = (gc >= 0) ? (LOUT / 128) * 4 : 0;   // 512 gather CTAs

    if ((int)blockIdx.x < gGrid) {
        // ================= GATHER: chunk gc =================
        // CTA = (l tile of 128) x (64-bc sub-slice). lane gathers half2 ->
        // warp load = 128B fully-used. 9 loads batched per l, tree-reduce.
        __half* s_out = (__half*)sm_raw;               // [128][66]

        const int gidx  = blockIdx.x;
        const int lTile = gidx >> 2;
        const int sub   = gidx & 3;
        const int lBase = lTile * 128;

        int myIdx[KNB];
        const int myL = lBase + w * 16 + (lane & 15);  // lanes 16-31 mirror
        #pragma unroll
        for (int k = 0; k < KNB; k++)
            myIdx[k] = __ldg(nb + (size_t)k * LOUT + myL);

        const __half2* xb = (const __half2*)(g_buf + (size_t)(gc & 1) * CHUNK_EL)
                            + sub * 32 + lane;

        #pragma unroll 1
        for (int m = 0; m < 16; m += 4) {
            __half2 acc[4];
            #pragma unroll
            for (int j = 0; j < 4; j++) {
                __half2 v[KNB];
                #pragma unroll
                for (int k = 0; k < KNB; k++) {
                    int i = __shfl_sync(0xffffffffu, myIdx[k], m + j);
                    v[k] = __ldg(xb + (size_t)i * 128);   // row stride 256 halves
                }
                __half2 m01 = __hmax2(v[0], v[1]);
                __half2 m23 = __hmax2(v[2], v[3]);
                __half2 m45 = __hmax2(v[4], v[5]);
                __half2 m67 = __hmax2(v[6], v[7]);
                m01 = __hmax2(m01, m23);
                m45 = __hmax2(m45, m67);
                acc[j] = __hmax2(__hmax2(m01, m45), v[8]);
            }
            const int ll = w * 16 + m;
            __half2* so = (__half2*)s_out;
            #pragma unroll
            for (int j = 0; j < 4; j++)
                so[(ll + j) * 33 + lane] = acc[j];   // bank (ll+j+lane)%32: free
        }
        __syncthreads();

        // writeback: t -> l = t&127, bc group (t>>7)*32; 128B coalesced stores
        const int l = t & 127;
        const int g = (t >> 7) * 32;
        float* ob = out + (size_t)(gc * CHUNK_BC + sub * 64 + g) * LOUT + lBase + l;
        #pragma unroll
        for (int b = 0; b < 32; b++)
            __stcs(ob + (size_t)b * LOUT, __half2float(s_out[l * 66 + g + b]));

    } else if (tc >= 0) {
        // ================= TRANSPOSE: chunk tc =================
        // Tile: 64 bc x 64 i. Scalar STS (row stride 65 floats: not 16B-aligned).
        float (*tile)[65] = (float (*)[65])sm_raw;

        const int tidx   = blockIdx.x - gGrid;
        const int iBase  = (tidx >> 2) * 64;
        const int bcT    = tidx & 3;
        const int bcBase = tc * CHUNK_BC + bcT * 64;

        const int r = t >> 2;    // bc row 0..63
        const int q = t & 3;     // 0..3
        const float4* x4 = (const float4*)(x + (size_t)(bcBase + r) * LIN + iBase);
        #pragma unroll
        for (int m = 0; m < 4; m++) {
            float4 v = __ldcs(x4 + q + 4 * m);   // streaming: don't evict scratch
            int c = (q + 4 * m) * 4;
            tile[r][c + 0] = v.x;
            tile[r][c + 1] = v.y;
            tile[r][c + 2] = v.z;
            tile[r][c + 3] = v.w;
        }
        __syncthreads();

        // store: warp w owns i = w*8..w*8+7; per i warp writes 128B contiguous
        __half2* dst = (__half2*)(g_buf + (size_t)(tc & 1) * CHUNK_EL)
                       + bcT * 32 + lane;
        #pragma unroll
        for (int s = 0; s < 8; s++) {
            int i = w * 8 + s;
            // tile[2lane][i]: bank (2lane+i)%32 -> 2-way max
            __half2 v = __floats2half2_rn(tile[2 * lane][i], tile[2 * lane + 1][i]);
            dst[(size_t)(iBase + i) * 128] = v;
        }
    }
}

// ---------------------------------------------------------------------------
extern "C" void kernel_launch(void* const* d_in, const int* in_sizes, int n_in,
                              void* d_out, int out_size) {
    const float* x   = (const float*)d_in[0];
    const int*   nb  = (const int*)d_in[1];
    float*       out = (float*)d_out;

    (void)in_sizes; (void)n_in; (void)out_size;

    const int TGRID = (LIN / 64) * (CHUNK_BC / 64);   // 4096
    const int GGRID = (LOUT / 128) * 4;               // 512

    pool_kernel<<<TGRID, 256>>>(x, nb, out, -1, 0);           // T0
    pool_kernel<<<GGRID + TGRID, 256>>>(x, nb, out, 0, 1);    // G0 || T1
    pool_kernel<<<GGRID + TGRID, 256>>>(x, nb, out, 1, 2);    // G1 || T2
    pool_kernel<<<GGRID + TGRID, 256>>>(x, nb, out, 2, 3);    // G2 || T3
    pool_kernel<<<GGRID, 256>>>(x, nb, out, 3, -1);           // G3
}